// round 16
// baseline (speedup 1.0000x reference)
#include <cuda_runtime.h>
#include <cuda_bf16.h>
#include <math.h>
#include <stdint.h>

#define BATCH   2
#define SEQ     2048
#define DMODEL  2048
#define NHEAD   16
#define DHEAD   128
#define DFF     8192
#define NTOK    (BATCH*SEQ)
#define LN_EPS  1e-5f
#define SCL 0.08838834764831845f

typedef __nv_bfloat16 bf16;

// ---------------- scratch ----------------
__device__ float g_TMP[NTOK*DMODEL];
__device__ float g_X1 [NTOK*DMODEL];
__device__ bf16 g_xh [NTOK*DMODEL];
__device__ bf16 g_xl [NTOK*DMODEL];
__device__ bf16 g_Qh [NTOK*DMODEL];
__device__ bf16 g_Ql [NTOK*DMODEL];
__device__ bf16 g_Kh [NTOK*DMODEL];
__device__ bf16 g_Kl [NTOK*DMODEL];
__device__ bf16 g_Vh [NTOK*DMODEL];
__device__ bf16 g_Vl [NTOK*DMODEL];
__device__ bf16 g_Abh[NTOK*DMODEL];
__device__ bf16 g_Abl[NTOK*DMODEL];
__device__ bf16 g_X1h[NTOK*DMODEL];
__device__ bf16 g_X1l[NTOK*DMODEL];
__device__ bf16 g_H1h[NTOK*DFF];
__device__ bf16 g_H1l[NTOK*DFF];
__device__ bf16 g_WqTh[DMODEL*DMODEL];
__device__ bf16 g_WqTl[DMODEL*DMODEL];
__device__ bf16 g_WkTh[DMODEL*DMODEL];
__device__ bf16 g_WkTl[DMODEL*DMODEL];
__device__ bf16 g_WvTh[DMODEL*DMODEL];
__device__ bf16 g_WvTl[DMODEL*DMODEL];
__device__ bf16 g_WoTh[DMODEL*DMODEL];
__device__ bf16 g_WoTl[DMODEL*DMODEL];
__device__ bf16 g_W1Th[DMODEL*DFF];
__device__ bf16 g_W1Tl[DMODEL*DFF];
__device__ bf16 g_W2Th[DMODEL*DFF];
__device__ bf16 g_W2Tl[DMODEL*DFF];

// ---------------- helpers ----------------
__device__ __forceinline__ uint32_t smem_u32(const void* p){ return (uint32_t)__cvta_generic_to_shared(p); }
__device__ __forceinline__ void cp_async16(uint32_t dst, const void* src){
    asm volatile("cp.async.cg.shared.global [%0], [%1], 16;\n"::"r"(dst),"l"(__cvta_generic_to_global(src)));
}
__device__ __forceinline__ void cp_commit(){ asm volatile("cp.async.commit_group;\n":::"memory"); }
template<int N> __device__ __forceinline__ void cp_wait(){ asm volatile("cp.async.wait_group %0;\n"::"n"(N):"memory"); }

__device__ __forceinline__ void mma_bf16(float* d, const uint32_t* a, const uint32_t* b){
    asm volatile(
        "mma.sync.aligned.m16n8k16.row.col.f32.bf16.bf16.f32 "
        "{%0,%1,%2,%3}, {%4,%5,%6,%7}, {%8,%9}, {%0,%1,%2,%3};"
        : "+f"(d[0]), "+f"(d[1]), "+f"(d[2]), "+f"(d[3])
        : "r"(a[0]), "r"(a[1]), "r"(a[2]), "r"(a[3]), "r"(b[0]), "r"(b[1]));
}
__device__ __forceinline__ void ldsm_x4(uint32_t& d0, uint32_t& d1, uint32_t& d2, uint32_t& d3, uint32_t addr){
    asm volatile("ldmatrix.sync.aligned.m8n8.x4.shared.b16 {%0,%1,%2,%3}, [%4];"
                 :"=r"(d0),"=r"(d1),"=r"(d2),"=r"(d3):"r"(addr));
}
__device__ __forceinline__ void ldsm_x2_t(uint32_t& b0, uint32_t& b1, uint32_t addr){
    asm volatile("ldmatrix.sync.aligned.m8n8.x2.trans.shared.b16 {%0,%1}, [%2];"
                 :"=r"(b0),"=r"(b1):"r"(addr));
}
__device__ __forceinline__ void split_bf16(float x, bf16& h, bf16& l){
    h = __float2bfloat16_rn(x);
    l = __float2bfloat16_rn(x - __bfloat162float(h));
}
__device__ __forceinline__ uint32_t pack2(bf16 a, bf16 b){
    __nv_bfloat162 v(a, b);
    return *(uint32_t*)&v;
}

// ---------------- split kernels ----------------
__global__ __launch_bounds__(256)
void act_split(const float* __restrict__ in, bf16* __restrict__ hi, bf16* __restrict__ lo, int n4)
{
    int i = blockIdx.x*256 + threadIdx.x;
    if (i >= n4) return;
    float4 v = ((const float4*)in)[i];
    bf16 h0,l0,h1,l1,h2,l2,h3,l3;
    split_bf16(v.x,h0,l0); split_bf16(v.y,h1,l1); split_bf16(v.z,h2,l2); split_bf16(v.w,h3,l3);
    uint32_t* hp = (uint32_t*)(hi + (size_t)i*4);
    uint32_t* lp = (uint32_t*)(lo + (size_t)i*4);
    hp[0]=pack2(h0,h1); hp[1]=pack2(h2,h3);
    lp[0]=pack2(l0,l1); lp[1]=pack2(l2,l3);
}

__global__ __launch_bounds__(256)
void wsplit_T(const float* __restrict__ in, bf16* __restrict__ hiT, bf16* __restrict__ loT, int K, int N)
{
    __shared__ float t[32][33];
    int x = blockIdx.x*32 + threadIdx.x;
    int y0 = blockIdx.y*32;
    #pragma unroll
    for (int j = threadIdx.y; j < 32; j += 8) t[j][threadIdx.x] = in[(size_t)(y0+j)*N + x];
    __syncthreads();
    int kk = y0 + threadIdx.x;
    #pragma unroll
    for (int j = threadIdx.y; j < 32; j += 8) {
        int n = blockIdx.x*32 + j;
        bf16 h, l;
        split_bf16(t[threadIdx.x][j], h, l);
        hiT[(size_t)n*K + kk] = h;
        loT[(size_t)n*K + kk] = l;
    }
}

// ---------------- bf16x3 mma GEMM: BM=256 x BN=128, 512 thr, 16 warps ----------------
#define BM 256
#define BN 128
#define BK 16
#define GTH 512
#define STAGES 4
#define KP 24
#define A_MAT (256*KP*2)          // 12288 B
#define B_MAT (128*KP*2)          // 6144 B
#define STG_B (2*A_MAT + 2*B_MAT) // 36864 B
#define GEMM_SMEM (STAGES*STG_B)  // 147456 B

__device__ __forceinline__ void g_load_stage(const bf16* Ah, const bf16* Al,
                                             const bf16* Bh, const bf16* Bl,
                                             int K, char* stage, int k0, int tid)
{
    uint32_t base = smem_u32(stage);
    #pragma unroll
    for (int q = 0; q < 3; q++) {
        int i = q*GTH + tid;          // 1536 chunks
        if (i < 1024) {               // A: 2 mats x 256 rows x 2 chunks
            int mat = i >> 9;
            int r = (i >> 1) & 255;
            int c = i & 1;
            const bf16* src = mat ? Al : Ah;
            cp_async16(base + mat*A_MAT + r*48 + c*16, src + (size_t)r*K + k0 + c*8);
        } else {                      // B: 2 mats x 128 rows x 2 chunks
            int j = i - 1024;
            int mat = j >> 8;
            int r = (j >> 1) & 127;
            int c = j & 1;
            const bf16* src = mat ? Bl : Bh;
            cp_async16(base + 2*A_MAT + mat*B_MAT + r*48 + c*16, src + (size_t)r*K + k0 + c*8);
        }
    }
    cp_commit();
}

// act: 0 none, 1 gelu, 2 scale by SCL
__device__ __forceinline__ void gemm_body(const bf16* Ah, const bf16* Al,
                                          const bf16* Bh, const bf16* Bl,
                                          const float* bias, float* Cf,
                                          bf16* Ch, bf16* Cl,
                                          int M, int N, int K, int act,
                                          char* gsm, int m0, int n0)
{
    const int tid  = threadIdx.x;
    const int lane = tid & 31, wid = tid >> 5;   // 16 warps
    const int wm = (wid & 7) * 32;               // 8 row positions (256 rows)
    const int wn = (wid >> 3) * 64;              // 2 col positions (128 cols)
    const int lq = lane >> 2;
    const int lr = lane & 3;

    const int a_lrow = lane & 15;
    const int a_lcol = (lane >> 4) << 3;
    const int b_lrow = (lane & 7) + ((lane >> 4) << 3);
    const int b_lcol = lane & 8;

    const bf16* Ahg = Ah + (size_t)m0 * K;
    const bf16* Alg = Al + (size_t)m0 * K;
    const bf16* Bhg = Bh + (size_t)n0 * K;
    const bf16* Blg = Bl + (size_t)n0 * K;

    float acc[2][8][4];
    #pragma unroll
    for (int i = 0; i < 2; i++) {
        #pragma unroll
        for (int j = 0; j < 8; j++) {
            #pragma unroll
            for (int k = 0; k < 4; k++) acc[i][j][k] = 0.f;
        }
    }

    const int nch = K / BK;
    for (int j = 0; j < STAGES - 1; j++)
        g_load_stage(Ahg, Alg, Bhg, Blg, K, gsm + j*STG_B, j*BK, tid);

    #pragma unroll 1
    for (int it = 0; it < nch; ++it) {
        cp_wait<STAGES - 2>();
        __syncthreads();
        const int buf = it % STAGES;
        const bf16* As_h = (const bf16*)(gsm + buf*STG_B);
        const bf16* As_l = (const bf16*)(gsm + buf*STG_B + A_MAT);
        const bf16* Bs_h = (const bf16*)(gsm + buf*STG_B + 2*A_MAT);
        const bf16* Bs_l = (const bf16*)(gsm + buf*STG_B + 2*A_MAT + B_MAT);

        const int j = it + STAGES - 1;
        if (j < nch)
            g_load_stage(Ahg, Alg, Bhg, Blg, K, gsm + (j % STAGES)*STG_B, j*BK, tid);

        uint32_t ah[2][4], al[2][4];
        #pragma unroll
        for (int mi = 0; mi < 2; mi++) {
            const int row = wm + mi*16 + a_lrow;
            ldsm_x4(ah[mi][0], ah[mi][1], ah[mi][2], ah[mi][3],
                    smem_u32(As_h + row*KP + a_lcol));
            ldsm_x4(al[mi][0], al[mi][1], al[mi][2], al[mi][3],
                    smem_u32(As_l + row*KP + a_lcol));
        }
        #pragma unroll
        for (int g = 0; g < 4; g++) {
            const int col = wn + g*16 + b_lrow;
            uint32_t bh[2][2], bl[2][2];
            ldsm_x4(bh[0][0], bh[0][1], bh[1][0], bh[1][1],
                    smem_u32(Bs_h + col*KP + b_lcol));
            ldsm_x4(bl[0][0], bl[0][1], bl[1][0], bl[1][1],
                    smem_u32(Bs_l + col*KP + b_lcol));
            #pragma unroll
            for (int p = 0; p < 2; p++) {
                #pragma unroll
                for (int mi = 0; mi < 2; mi++)
                    mma_bf16(acc[mi][2*g+p], ah[mi], bh[p]);
            }
            #pragma unroll
            for (int p = 0; p < 2; p++) {
                #pragma unroll
                for (int mi = 0; mi < 2; mi++)
                    mma_bf16(acc[mi][2*g+p], ah[mi], bl[p]);
            }
            #pragma unroll
            for (int p = 0; p < 2; p++) {
                #pragma unroll
                for (int mi = 0; mi < 2; mi++)
                    mma_bf16(acc[mi][2*g+p], al[mi], bh[p]);
            }
        }
    }

    #pragma unroll
    for (int mi = 0; mi < 2; mi++) {
        #pragma unroll
        for (int ni = 0; ni < 8; ni++) {
            const int r  = m0 + wm + mi*16 + lq;
            const int c  = n0 + wn + ni*8 + 2*lr;
            float b0 = bias[c], b1 = bias[c+1];
            float v0 = acc[mi][ni][0] + b0;
            float v1 = acc[mi][ni][1] + b1;
            float v2 = acc[mi][ni][2] + b0;
            float v3 = acc[mi][ni][3] + b1;
            if (act == 1) {
                v0 = 0.5f*v0*(1.0f + erff(v0*0.70710678118654752440f));
                v1 = 0.5f*v1*(1.0f + erff(v1*0.70710678118654752440f));
                v2 = 0.5f*v2*(1.0f + erff(v2*0.70710678118654752440f));
                v3 = 0.5f*v3*(1.0f + erff(v3*0.70710678118654752440f));
            } else if (act == 2) {
                v0 *= SCL; v1 *= SCL; v2 *= SCL; v3 *= SCL;
            }
            if (Cf) {
                float* cp0 = Cf + (size_t)r*N + c;
                float* cp1 = Cf + (size_t)(r+8)*N + c;
                cp0[0] = v0; cp0[1] = v1;
                cp1[0] = v2; cp1[1] = v3;
            }
            if (Ch) {
                bf16 h0,l0,h1,l1,h2,l2,h3,l3;
                split_bf16(v0,h0,l0); split_bf16(v1,h1,l1);
                split_bf16(v2,h2,l2); split_bf16(v3,h3,l3);
                *(uint32_t*)(Ch + (size_t)r*N + c)     = pack2(h0,h1);
                *(uint32_t*)(Ch + (size_t)(r+8)*N + c) = pack2(h2,h3);
                *(uint32_t*)(Cl + (size_t)r*N + c)     = pack2(l0,l1);
                *(uint32_t*)(Cl + (size_t)(r+8)*N + c) = pack2(l2,l3);
            }
        }
    }
}

__global__ __launch_bounds__(GTH, 1)
void gemm_bf16x3(const bf16* __restrict__ Ah, const bf16* __restrict__ Al,
                 const bf16* __restrict__ Bh, const bf16* __restrict__ Bl,
                 const float* __restrict__ bias, float* __restrict__ Cf,
                 bf16* __restrict__ Ch, bf16* __restrict__ Cl,
                 int M, int N, int K, int act)
{
    extern __shared__ char gsm[];
    gemm_body(Ah, Al, Bh, Bl, bias, Cf, Ch, Cl, M, N, K, act,
              gsm, blockIdx.y*BM, blockIdx.x*BN);
}

// fused QKV: blockIdx.z selects weight/bias/output triple
__global__ __launch_bounds__(GTH, 1)
void gemm_qkv(const bf16* __restrict__ Ah, const bf16* __restrict__ Al,
              const bf16* __restrict__ BhQ, const bf16* __restrict__ BlQ,
              const bf16* __restrict__ BhK, const bf16* __restrict__ BlK,
              const bf16* __restrict__ BhV, const bf16* __restrict__ BlV,
              const float* __restrict__ bq, const float* __restrict__ bk2,
              const float* __restrict__ bv,
              bf16* __restrict__ Qh, bf16* __restrict__ Ql,
              bf16* __restrict__ Kh, bf16* __restrict__ Kl,
              bf16* __restrict__ Vh, bf16* __restrict__ Vl)
{
    extern __shared__ char gsm[];
    const int z = blockIdx.z;
    const bf16 *Bh, *Bl;
    const float* bias;
    bf16 *Ch, *Cl;
    int act;
    if (z == 0)      { Bh = BhQ; Bl = BlQ; bias = bq;  Ch = Qh; Cl = Ql; act = 2; }
    else if (z == 1) { Bh = BhK; Bl = BlK; bias = bk2; Ch = Kh; Cl = Kl; act = 0; }
    else             { Bh = BhV; Bl = BlV; bias = bv;  Ch = Vh; Cl = Vl; act = 0; }
    gemm_body(Ah, Al, Bh, Bl, bias, nullptr, Ch, Cl, NTOK, DMODEL, DMODEL, act,
              gsm, blockIdx.y*BM, blockIdx.x*BN);
}

// ---------------- MMA flash attention (bf16x3, causal) ----------------
#define AST 136
#define AQR 128
#define ATH2 256
#define ABUF (4*64*AST)
#define ATT_SMEM ((2*AQR*AST + 2*ABUF)*2)

__device__ __forceinline__ void attn_load_chunk(const bf16* Kh, const bf16* Kl,
                                                const bf16* Vh, const bf16* Vl,
                                                size_t gbase, int k0, uint32_t sbuf, int tid)
{
    const bf16* srcs[4] = {Kh, Kl, Vh, Vl};
    #pragma unroll
    for (int t = 0; t < 4; t++) {
        const bf16* p = srcs[t] + gbase + (size_t)k0*DMODEL;
        #pragma unroll
        for (int q = 0; q < 4; q++) {
            int i = q*ATH2 + tid;
            int r = i >> 4, c = i & 15;
            cp_async16(sbuf + (t*64 + r)*(AST*2) + c*16, p + (size_t)r*DMODEL + c*8);
        }
    }
    cp_commit();
}

__global__ __launch_bounds__(ATH2, 1)
void attn_mma(const bf16* __restrict__ Qh, const bf16* __restrict__ Ql,
              const bf16* __restrict__ Kh, const bf16* __restrict__ Kl,
              const bf16* __restrict__ Vh, const bf16* __restrict__ Vl,
              bf16* __restrict__ Oh, bf16* __restrict__ Ol)
{
    extern __shared__ char asmem[];
    const int tid = threadIdx.x;
    const int lane = tid & 31, w = tid >> 5;
    const int lq = lane >> 2, lr = lane & 3;
    const int q0 = blockIdx.x * AQR;
    const int h = blockIdx.y, b = blockIdx.z;
    const size_t gbase = ((size_t)b*SEQ)*DMODEL + h*DHEAD;

    bf16* Qs_h = (bf16*)asmem;
    bf16* Qs_l = Qs_h + AQR*AST;
    bf16* bufs = Qs_l + AQR*AST;

    {
        const bf16* srcs[2] = {Qh, Ql};
        #pragma unroll
        for (int t = 0; t < 2; t++) {
            const bf16* p = srcs[t] + gbase + (size_t)q0*DMODEL;
            uint32_t dst = smem_u32(Qs_h + t*AQR*AST);
            #pragma unroll
            for (int q = 0; q < 8; q++) {
                int i = q*ATH2 + tid;
                int r = i >> 4, c = i & 15;
                cp_async16(dst + r*(AST*2) + c*16, p + (size_t)r*DMODEL + c*8);
            }
        }
        attn_load_chunk(Kh, Kl, Vh, Vl, gbase, 0, smem_u32(bufs), tid);
    }

    float o[16][4];
    #pragma unroll
    for (int i = 0; i < 16; i++) {
        #pragma unroll
        for (int j = 0; j < 4; j++) o[i][j] = 0.f;
    }
    float m0v = -1e30f, m1v = -1e30f, l0v = 0.f, l1v = 0.f;

    const int qb = w * 16;
    const int row0 = q0 + qb + lq, row1 = row0 + 8;
    const int nch = q0/64 + 2;

    #pragma unroll 1
    for (int ch = 0; ch < nch; ++ch) {
        const int k0 = ch * 64;
        const bf16* Ks_h = bufs + (ch & 1)*ABUF;
        const bf16* Ks_l = Ks_h + 64*AST;
        const bf16* Vs_h = Ks_h + 2*64*AST;
        const bf16* Vs_l = Ks_h + 3*64*AST;

        if (ch + 1 < nch) {
            attn_load_chunk(Kh, Kl, Vh, Vl, gbase, k0 + 64, smem_u32(bufs + ((ch+1)&1)*ABUF), tid);
            cp_wait<1>();
        } else {
            cp_wait<0>();
        }
        __syncthreads();

        float s[8][4];
        #pragma unroll
        for (int i = 0; i < 8; i++) {
            #pragma unroll
            for (int j = 0; j < 4; j++) s[i][j] = 0.f;
        }
        #pragma unroll
        for (int ks = 0; ks < 8; ks++) {
            const int kk = ks*16 + 2*lr;
            uint32_t ah[4], al[4];
            ah[0] = *(const uint32_t*)(Qs_h + (qb+lq)*AST + kk);
            ah[1] = *(const uint32_t*)(Qs_h + (qb+lq+8)*AST + kk);
            ah[2] = *(const uint32_t*)(Qs_h + (qb+lq)*AST + kk + 8);
            ah[3] = *(const uint32_t*)(Qs_h + (qb+lq+8)*AST + kk + 8);
            al[0] = *(const uint32_t*)(Qs_l + (qb+lq)*AST + kk);
            al[1] = *(const uint32_t*)(Qs_l + (qb+lq+8)*AST + kk);
            al[2] = *(const uint32_t*)(Qs_l + (qb+lq)*AST + kk + 8);
            al[3] = *(const uint32_t*)(Qs_l + (qb+lq+8)*AST + kk + 8);
            #pragma unroll
            for (int ni = 0; ni < 8; ni++) {
                const int col = ni*8 + lq;
                uint32_t bh[2], bl[2];
                bh[0] = *(const uint32_t*)(Ks_h + col*AST + kk);
                bh[1] = *(const uint32_t*)(Ks_h + col*AST + kk + 8);
                bl[0] = *(const uint32_t*)(Ks_l + col*AST + kk);
                bl[1] = *(const uint32_t*)(Ks_l + col*AST + kk + 8);
                mma_bf16(s[ni], ah, bh);
                mma_bf16(s[ni], ah, bl);
                mma_bf16(s[ni], al, bh);
            }
        }

        #pragma unroll
        for (int ni = 0; ni < 8; ni++) {
            const int c0 = k0 + ni*8 + 2*lr;
            if (c0     > row0) s[ni][0] = -1e30f;
            if (c0 + 1 > row0) s[ni][1] = -1e30f;
            if (c0     > row1) s[ni][2] = -1e30f;
            if (c0 + 1 > row1) s[ni][3] = -1e30f;
        }

        float mx0 = m0v, mx1 = m1v;
        #pragma unroll
        for (int ni = 0; ni < 8; ni++) {
            mx0 = fmaxf(mx0, fmaxf(s[ni][0], s[ni][1]));
            mx1 = fmaxf(mx1, fmaxf(s[ni][2], s[ni][3]));
        }
        mx0 = fmaxf(mx0, __shfl_xor_sync(~0u, mx0, 1));
        mx0 = fmaxf(mx0, __shfl_xor_sync(~0u, mx0, 2));
        mx1 = fmaxf(mx1, __shfl_xor_sync(~0u, mx1, 1));
        mx1 = fmaxf(mx1, __shfl_xor_sync(~0u, mx1, 2));
        float c0f = __expf(m0v - mx0), c1f = __expf(m1v - mx1);
        float ls0 = 0.f, ls1 = 0.f;
        #pragma unroll
        for (int ni = 0; ni < 8; ni++) {
            s[ni][0] = __expf(s[ni][0] - mx0);
            s[ni][1] = __expf(s[ni][1] - mx0);
            s[ni][2] = __expf(s[ni][2] - mx1);
            s[ni][3] = __expf(s[ni][3] - mx1);
            ls0 += s[ni][0] + s[ni][1];
            ls1 += s[ni][2] + s[ni][3];
        }
        ls0 += __shfl_xor_sync(~0u, ls0, 1);
        ls0 += __shfl_xor_sync(~0u, ls0, 2);
        ls1 += __shfl_xor_sync(~0u, ls1, 1);
        ls1 += __shfl_xor_sync(~0u, ls1, 2);
        m0v = mx0; m1v = mx1;
        l0v = l0v*c0f + ls0;
        l1v = l1v*c1f + ls1;
        #pragma unroll
        for (int nd = 0; nd < 16; nd++) {
            o[nd][0] *= c0f; o[nd][1] *= c0f;
            o[nd][2] *= c1f; o[nd][3] *= c1f;
        }

        #pragma unroll
        for (int ks = 0; ks < 4; ks++) {
            bf16 hh[8], ll[8];
            split_bf16(s[2*ks][0],   hh[0], ll[0]);
            split_bf16(s[2*ks][1],   hh[1], ll[1]);
            split_bf16(s[2*ks][2],   hh[2], ll[2]);
            split_bf16(s[2*ks][3],   hh[3], ll[3]);
            split_bf16(s[2*ks+1][0], hh[4], ll[4]);
            split_bf16(s[2*ks+1][1], hh[5], ll[5]);
            split_bf16(s[2*ks+1][2], hh[6], ll[6]);
            split_bf16(s[2*ks+1][3], hh[7], ll[7]);
            uint32_t ah[4], al[4];
            ah[0] = pack2(hh[0], hh[1]); ah[1] = pack2(hh[2], hh[3]);
            ah[2] = pack2(hh[4], hh[5]); ah[3] = pack2(hh[6], hh[7]);
            al[0] = pack2(ll[0], ll[1]); al[1] = pack2(ll[2], ll[3]);
            al[2] = pack2(ll[4], ll[5]); al[3] = pack2(ll[6], ll[7]);
            const int vrow = ks*16 + (lane & 15);
            #pragma unroll
            for (int nd = 0; nd < 16; nd++) {
                uint32_t bh[2], bl[2];
                ldsm_x2_t(bh[0], bh[1], smem_u32(Vs_h + vrow*AST + nd*8));
                ldsm_x2_t(bl[0], bl[1], smem_u32(Vs_l + vrow*AST + nd*8));
                mma_bf16(o[nd], ah, bh);
                mma_bf16(o[nd], ah, bl);
                mma_bf16(o[nd], al, bh);
            }
        }
        __syncthreads();
    }

    const float inv0 = 1.f / l0v, inv1 = 1.f / l1v;
    const size_t r0 = ((size_t)b*SEQ + row0)*DMODEL + h*DHEAD;
    const size_t r1 = ((size_t)b*SEQ + row1)*DMODEL + h*DHEAD;
    #pragma unroll
    for (int nd = 0; nd < 16; nd++) {
        const int c = nd*8 + 2*lr;
        bf16 h0,l0,h1,l1,h2,l2,h3,l3;
        split_bf16(o[nd][0]*inv0, h0, l0);
        split_bf16(o[nd][1]*inv0, h1, l1);
        split_bf16(o[nd][2]*inv1, h2, l2);
        split_bf16(o[nd][3]*inv1, h3, l3);
        *(uint32_t*)(Oh + r0 + c) = pack2(h0, h1);
        *(uint32_t*)(Ol + r0 + c) = pack2(l0, l1);
        *(uint32_t*)(Oh + r1 + c) = pack2(h2, h3);
        *(uint32_t*)(Ol + r1 + c) = pack2(l2, l3);
    }
}

// ---------------- fused residual + LayerNorm (+ optional splits) ----------------
__global__ __launch_bounds__(256)
void ln_residual(const float* __restrict__ x, const float* __restrict__ r,
                 const float* __restrict__ g, const float* __restrict__ be,
                 float* __restrict__ out, bf16* __restrict__ oh, bf16* __restrict__ ol)
{
    const int row = blockIdx.x, t = threadIdx.x;
    const float* xp = x + (size_t)row*DMODEL;
    const float* rp = r + (size_t)row*DMODEL;
    float v[8], s = 0.f, s2 = 0.f;
    #pragma unroll
    for (int i = 0; i < 8; i++) {
        int c = t + i*256;
        float vv = xp[c]+rp[c];
        v[i] = vv; s += vv; s2 += vv*vv;
    }
    __shared__ float red[64];
    #pragma unroll
    for (int o = 16; o > 0; o >>= 1) {
        s  += __shfl_xor_sync(~0u,s,o);
        s2 += __shfl_xor_sync(~0u,s2,o);
    }
    int wid = t>>5, lid = t&31;
    if (lid == 0) { red[wid] = s; red[32+wid] = s2; }
    __syncthreads();
    if (wid == 0) {
        float a = (lid<8)?red[lid]:0.f, bsum = (lid<8)?red[32+lid]:0.f;
        #pragma unroll
        for (int o = 4; o > 0; o >>= 1) {
            a    += __shfl_xor_sync(~0u,a,o);
            bsum += __shfl_xor_sync(~0u,bsum,o);
        }
        if (lid == 0) { red[0] = a; red[1] = bsum; }
    }
    __syncthreads();
    float mean = red[0]*(1.f/DMODEL);
    float var  = red[1]*(1.f/DMODEL) - mean*mean;
    float rstd = rsqrtf(var + LN_EPS);
    #pragma unroll
    for (int i = 0; i < 8; i++) {
        int c = t + i*256;
        float y = g[c]*(v[i]-mean)*rstd + be[c];
        if (out) out[(size_t)row*DMODEL + c] = y;
        if (oh) {
            bf16 hh, lll;
            split_bf16(y, hh, lll);
            oh[(size_t)row*DMODEL + c] = hh;
            ol[(size_t)row*DMODEL + c] = lll;
        }
    }
}

// ---------------- launch ----------------
static float* SYM(const void* s){ void* p; cudaGetSymbolAddress(&p, (const void*)s); return (float*)p; }

extern "C" void kernel_launch(void* const* d_in, const int* in_sizes, int n_in,
                              void* d_out, int out_size)
{
    (void)in_sizes; (void)n_in; (void)out_size;
    const float* x  = (const float*)d_in[0];
    const float* Wq = (const float*)d_in[2];  const float* bq = (const float*)d_in[3];
    const float* Wk = (const float*)d_in[4];  const float* bk = (const float*)d_in[5];
    const float* Wv = (const float*)d_in[6];  const float* bv = (const float*)d_in[7];
    const float* Wo = (const float*)d_in[8];  const float* bo = (const float*)d_in[9];
    const float* W1 = (const float*)d_in[10]; const float* b1 = (const float*)d_in[11];
    const float* W2 = (const float*)d_in[12]; const float* b2 = (const float*)d_in[13];
    const float* g1 = (const float*)d_in[14]; const float* be1= (const float*)d_in[15];
    const float* g2 = (const float*)d_in[16]; const float* be2= (const float*)d_in[17];
    float* out = (float*)d_out;

    float *Tb = SYM(g_TMP), *X1b = SYM(g_X1);
    bf16 *xh = (bf16*)SYM(g_xh),  *xl = (bf16*)SYM(g_xl);
    bf16 *Qh = (bf16*)SYM(g_Qh),  *Ql = (bf16*)SYM(g_Ql);
    bf16 *Kh = (bf16*)SYM(g_Kh),  *Kl = (bf16*)SYM(g_Kl);
    bf16 *Vh = (bf16*)SYM(g_Vh),  *Vl = (bf16*)SYM(g_Vl);
    bf16 *Abh= (bf16*)SYM(g_Abh), *Abl= (bf16*)SYM(g_Abl);
    bf16 *X1h= (bf16*)SYM(g_X1h), *X1l= (bf16*)SYM(g_X1l);
    bf16 *H1h= (bf16*)SYM(g_H1h), *H1l= (bf16*)SYM(g_H1l);
    bf16 *WqTh=(bf16*)SYM(g_WqTh),*WqTl=(bf16*)SYM(g_WqTl);
    bf16 *WkTh=(bf16*)SYM(g_WkTh),*WkTl=(bf16*)SYM(g_WkTl);
    bf16 *WvTh=(bf16*)SYM(g_WvTh),*WvTl=(bf16*)SYM(g_WvTl);
    bf16 *WoTh=(bf16*)SYM(g_WoTh),*WoTl=(bf16*)SYM(g_WoTl);
    bf16 *W1Th=(bf16*)SYM(g_W1Th),*W1Tl=(bf16*)SYM(g_W1Tl);
    bf16 *W2Th=(bf16*)SYM(g_W2Th),*W2Tl=(bf16*)SYM(g_W2Tl);

    cudaFuncSetAttribute(gemm_bf16x3, cudaFuncAttributeMaxDynamicSharedMemorySize, GEMM_SMEM);
    cudaFuncSetAttribute(gemm_qkv,    cudaFuncAttributeMaxDynamicSharedMemorySize, GEMM_SMEM);
    cudaFuncSetAttribute(attn_mma,    cudaFuncAttributeMaxDynamicSharedMemorySize, ATT_SMEM);

    const int M = NTOK;
    dim3 tb(32,8);
    dim3 gDD(DMODEL/BN, M/BM);       // 16 x 16
    dim3 gQKV(DMODEL/BN, M/BM, 3);
    dim3 gDF(DFF/BN,    M/BM);       // 64 x 16
    const int nDD4 = NTOK*DMODEL/4;

    act_split<<<(nDD4+255)/256, 256>>>(x, xh, xl, nDD4);
    wsplit_T<<<dim3(DMODEL/32, DMODEL/32), tb>>>(Wq, WqTh, WqTl, DMODEL, DMODEL);
    wsplit_T<<<dim3(DMODEL/32, DMODEL/32), tb>>>(Wk, WkTh, WkTl, DMODEL, DMODEL);
    wsplit_T<<<dim3(DMODEL/32, DMODEL/32), tb>>>(Wv, WvTh, WvTl, DMODEL, DMODEL);

    gemm_qkv<<<gQKV, GTH, GEMM_SMEM>>>(xh, xl,
                                       WqTh, WqTl, WkTh, WkTl, WvTh, WvTl,
                                       bq, bk, bv, Qh, Ql, Kh, Kl, Vh, Vl);

    wsplit_T<<<dim3(DMODEL/32, DMODEL/32), tb>>>(Wo, WoTh, WoTl, DMODEL, DMODEL);
    wsplit_T<<<dim3(DFF/32,    DMODEL/32), tb>>>(W1, W1Th, W1Tl, DMODEL, DFF);
    wsplit_T<<<dim3(DMODEL/32, DFF/32),    tb>>>(W2, W2Th, W2Tl, DFF, DMODEL);

    attn_mma<<<dim3(SEQ/AQR, NHEAD, BATCH), ATH2, ATT_SMEM>>>(Qh, Ql, Kh, Kl, Vh, Vl, Abh, Abl);

    gemm_bf16x3<<<gDD, GTH, GEMM_SMEM>>>(Abh, Abl, WoTh, WoTl, bo, Tb, nullptr, nullptr, M, DMODEL, DMODEL, 0);
    ln_residual<<<NTOK, 256>>>(x, Tb, g1, be1, X1b, X1h, X1l);

    gemm_bf16x3<<<gDF, GTH, GEMM_SMEM>>>(X1h, X1l, W1Th, W1Tl, b1, nullptr, H1h, H1l, M, DFF, DMODEL, 1);
    gemm_bf16x3<<<gDD, GTH, GEMM_SMEM>>>(H1h, H1l, W2Th, W2Tl, b2, Tb, nullptr, nullptr, M, DMODEL, DFF, 0);

    ln_residual<<<NTOK, 256>>>(X1b, Tb, g2, be2, out, nullptr, nullptr);
}

// round 17
// speedup vs baseline: 1.0200x; 1.0200x over previous
#include <cuda_runtime.h>
#include <cuda_bf16.h>
#include <math.h>
#include <stdint.h>

#define BATCH   2
#define SEQ     2048
#define DMODEL  2048
#define NHEAD   16
#define DHEAD   128
#define DFF     8192
#define NTOK    (BATCH*SEQ)
#define LN_EPS  1e-5f
#define SCL 0.08838834764831845f

typedef __nv_bfloat16 bf16;

// ---------------- scratch ----------------
__device__ float g_TMP[NTOK*DMODEL];
__device__ float g_X1 [NTOK*DMODEL];
__device__ bf16 g_xh [NTOK*DMODEL];
__device__ bf16 g_xl [NTOK*DMODEL];
__device__ bf16 g_Qh [NTOK*DMODEL];
__device__ bf16 g_Ql [NTOK*DMODEL];
__device__ bf16 g_Kh [NTOK*DMODEL];
__device__ bf16 g_Kl [NTOK*DMODEL];
__device__ bf16 g_Vh [NTOK*DMODEL];
__device__ bf16 g_Vl [NTOK*DMODEL];
__device__ bf16 g_Abh[NTOK*DMODEL];
__device__ bf16 g_Abl[NTOK*DMODEL];
__device__ bf16 g_X1h[NTOK*DMODEL];
__device__ bf16 g_X1l[NTOK*DMODEL];
__device__ bf16 g_H1h[NTOK*DFF];
__device__ bf16 g_H1l[NTOK*DFF];
__device__ bf16 g_WqTh[DMODEL*DMODEL];
__device__ bf16 g_WqTl[DMODEL*DMODEL];
__device__ bf16 g_WkTh[DMODEL*DMODEL];
__device__ bf16 g_WkTl[DMODEL*DMODEL];
__device__ bf16 g_WvTh[DMODEL*DMODEL];
__device__ bf16 g_WvTl[DMODEL*DMODEL];
__device__ bf16 g_WoTh[DMODEL*DMODEL];
__device__ bf16 g_WoTl[DMODEL*DMODEL];
__device__ bf16 g_W1Th[DMODEL*DFF];
__device__ bf16 g_W1Tl[DMODEL*DFF];
__device__ bf16 g_W2Th[DMODEL*DFF];
__device__ bf16 g_W2Tl[DMODEL*DFF];

// ---------------- helpers ----------------
__device__ __forceinline__ uint32_t smem_u32(const void* p){ return (uint32_t)__cvta_generic_to_shared(p); }
__device__ __forceinline__ void cp_async16(uint32_t dst, const void* src){
    asm volatile("cp.async.cg.shared.global [%0], [%1], 16;\n"::"r"(dst),"l"(__cvta_generic_to_global(src)));
}
__device__ __forceinline__ void cp_commit(){ asm volatile("cp.async.commit_group;\n":::"memory"); }
template<int N> __device__ __forceinline__ void cp_wait(){ asm volatile("cp.async.wait_group %0;\n"::"n"(N):"memory"); }

__device__ __forceinline__ void mma_bf16(float* d, const uint32_t* a, const uint32_t* b){
    asm volatile(
        "mma.sync.aligned.m16n8k16.row.col.f32.bf16.bf16.f32 "
        "{%0,%1,%2,%3}, {%4,%5,%6,%7}, {%8,%9}, {%0,%1,%2,%3};"
        : "+f"(d[0]), "+f"(d[1]), "+f"(d[2]), "+f"(d[3])
        : "r"(a[0]), "r"(a[1]), "r"(a[2]), "r"(a[3]), "r"(b[0]), "r"(b[1]));
}
__device__ __forceinline__ void ldsm_x4(uint32_t& d0, uint32_t& d1, uint32_t& d2, uint32_t& d3, uint32_t addr){
    asm volatile("ldmatrix.sync.aligned.m8n8.x4.shared.b16 {%0,%1,%2,%3}, [%4];"
                 :"=r"(d0),"=r"(d1),"=r"(d2),"=r"(d3):"r"(addr));
}
__device__ __forceinline__ void ldsm_x2_t(uint32_t& b0, uint32_t& b1, uint32_t addr){
    asm volatile("ldmatrix.sync.aligned.m8n8.x2.trans.shared.b16 {%0,%1}, [%2];"
                 :"=r"(b0),"=r"(b1):"r"(addr));
}
__device__ __forceinline__ void split_bf16(float x, bf16& h, bf16& l){
    h = __float2bfloat16_rn(x);
    l = __float2bfloat16_rn(x - __bfloat162float(h));
}
__device__ __forceinline__ uint32_t pack2(bf16 a, bf16 b){
    __nv_bfloat162 v(a, b);
    return *(uint32_t*)&v;
}

// ---------------- split kernels ----------------
__global__ __launch_bounds__(256)
void act_split(const float* __restrict__ in, bf16* __restrict__ hi, bf16* __restrict__ lo, int n4)
{
    int i = blockIdx.x*256 + threadIdx.x;
    if (i >= n4) return;
    float4 v = ((const float4*)in)[i];
    bf16 h0,l0,h1,l1,h2,l2,h3,l3;
    split_bf16(v.x,h0,l0); split_bf16(v.y,h1,l1); split_bf16(v.z,h2,l2); split_bf16(v.w,h3,l3);
    uint32_t* hp = (uint32_t*)(hi + (size_t)i*4);
    uint32_t* lp = (uint32_t*)(lo + (size_t)i*4);
    hp[0]=pack2(h0,h1); hp[1]=pack2(h2,h3);
    lp[0]=pack2(l0,l1); lp[1]=pack2(l2,l3);
}

__global__ __launch_bounds__(256)
void wsplit_T(const float* __restrict__ in, bf16* __restrict__ hiT, bf16* __restrict__ loT, int K, int N)
{
    __shared__ float t[32][33];
    int x = blockIdx.x*32 + threadIdx.x;
    int y0 = blockIdx.y*32;
    #pragma unroll
    for (int j = threadIdx.y; j < 32; j += 8) t[j][threadIdx.x] = in[(size_t)(y0+j)*N + x];
    __syncthreads();
    int kk = y0 + threadIdx.x;
    #pragma unroll
    for (int j = threadIdx.y; j < 32; j += 8) {
        int n = blockIdx.x*32 + j;
        bf16 h, l;
        split_bf16(t[threadIdx.x][j], h, l);
        hiT[(size_t)n*K + kk] = h;
        loT[(size_t)n*K + kk] = l;
    }
}

// ---------------- bf16x3 mma GEMM core (R15 config: 128x128, 256 thr, 2 CTA/SM) ----------------
#define BM 128
#define BN 128
#define BK 16
#define STAGES 4
#define KP 24
#define MAT_B (128*KP*2)
#define STG_B (4*MAT_B)
#define GEMM_SMEM (STAGES*STG_B)

__device__ __forceinline__ void g_load_stage(const bf16* Ah, const bf16* Al,
                                             const bf16* Bh, const bf16* Bl,
                                             int K, char* stage, int k0, int tid)
{
    uint32_t base = smem_u32(stage);
    const bf16* srcs[4] = {Ah, Al, Bh, Bl};
    #pragma unroll
    for (int q = 0; q < 4; q++) {
        int r = tid >> 1, c = tid & 1;
        cp_async16(base + q*MAT_B + r*48 + c*16, srcs[q] + (size_t)r*K + k0 + c*8);
    }
    cp_commit();
}

// act: 0 none, 1 gelu, 2 scale by SCL
__device__ __forceinline__ void gemm_body(const bf16* Ah, const bf16* Al,
                                          const bf16* Bh, const bf16* Bl,
                                          const float* bias, float* Cf,
                                          bf16* Ch, bf16* Cl,
                                          int M, int N, int K, int act,
                                          char* gsm, int m0, int n0)
{
    const int tid  = threadIdx.x;
    const int lane = tid & 31, wid = tid >> 5;
    const int wm = (wid & 3) * 32;
    const int wn = (wid >> 2) * 64;
    const int lq = lane >> 2;
    const int lr = lane & 3;

    const int a_lrow = lane & 15;
    const int a_lcol = (lane >> 4) << 3;
    const int b_lrow = (lane & 7) + ((lane >> 4) << 3);
    const int b_lcol = lane & 8;

    const bf16* Ahg = Ah + (size_t)m0 * K;
    const bf16* Alg = Al + (size_t)m0 * K;
    const bf16* Bhg = Bh + (size_t)n0 * K;
    const bf16* Blg = Bl + (size_t)n0 * K;

    float acc[2][8][4];
    #pragma unroll
    for (int i = 0; i < 2; i++) {
        #pragma unroll
        for (int j = 0; j < 8; j++) {
            #pragma unroll
            for (int k = 0; k < 4; k++) acc[i][j][k] = 0.f;
        }
    }

    const int nch = K / BK;
    for (int j = 0; j < STAGES - 1; j++)
        g_load_stage(Ahg, Alg, Bhg, Blg, K, gsm + j*STG_B, j*BK, tid);

    #pragma unroll 1
    for (int it = 0; it < nch; ++it) {
        cp_wait<STAGES - 2>();
        __syncthreads();
        const int buf = it % STAGES;
        const bf16* As_h = (const bf16*)(gsm + buf*STG_B);
        const bf16* As_l = (const bf16*)(gsm + buf*STG_B + MAT_B);
        const bf16* Bs_h = (const bf16*)(gsm + buf*STG_B + 2*MAT_B);
        const bf16* Bs_l = (const bf16*)(gsm + buf*STG_B + 3*MAT_B);

        const int j = it + STAGES - 1;
        if (j < nch)
            g_load_stage(Ahg, Alg, Bhg, Blg, K, gsm + (j % STAGES)*STG_B, j*BK, tid);

        uint32_t ah[2][4], al[2][4], bhreg[4][2][2];
        #pragma unroll
        for (int mi = 0; mi < 2; mi++) {
            const int row = wm + mi*16 + a_lrow;
            ldsm_x4(ah[mi][0], ah[mi][1], ah[mi][2], ah[mi][3],
                    smem_u32(As_h + row*KP + a_lcol));
            ldsm_x4(al[mi][0], al[mi][1], al[mi][2], al[mi][3],
                    smem_u32(As_l + row*KP + a_lcol));
        }
        #pragma unroll
        for (int g = 0; g < 4; g++) {
            const int col = wn + g*16 + b_lrow;
            ldsm_x4(bhreg[g][0][0], bhreg[g][0][1], bhreg[g][1][0], bhreg[g][1][1],
                    smem_u32(Bs_h + col*KP + b_lcol));
        }
        #pragma unroll
        for (int g = 0; g < 4; g++) {
            #pragma unroll
            for (int p = 0; p < 2; p++) {
                #pragma unroll
                for (int mi = 0; mi < 2; mi++)
                    mma_bf16(acc[mi][2*g+p], ah[mi], bhreg[g][p]);
            }
        }
        #pragma unroll
        for (int g = 0; g < 4; g++) {
            const int col = wn + g*16 + b_lrow;
            uint32_t bl[2][2];
            ldsm_x4(bl[0][0], bl[0][1], bl[1][0], bl[1][1],
                    smem_u32(Bs_l + col*KP + b_lcol));
            #pragma unroll
            for (int p = 0; p < 2; p++) {
                #pragma unroll
                for (int mi = 0; mi < 2; mi++)
                    mma_bf16(acc[mi][2*g+p], ah[mi], bl[p]);
            }
        }
        #pragma unroll
        for (int g = 0; g < 4; g++) {
            #pragma unroll
            for (int p = 0; p < 2; p++) {
                #pragma unroll
                for (int mi = 0; mi < 2; mi++)
                    mma_bf16(acc[mi][2*g+p], al[mi], bhreg[g][p]);
            }
        }
    }

    #pragma unroll
    for (int mi = 0; mi < 2; mi++) {
        #pragma unroll
        for (int ni = 0; ni < 8; ni++) {
            const int r  = m0 + wm + mi*16 + lq;
            const int c  = n0 + wn + ni*8 + 2*lr;
            float b0 = bias[c], b1 = bias[c+1];
            float v0 = acc[mi][ni][0] + b0;
            float v1 = acc[mi][ni][1] + b1;
            float v2 = acc[mi][ni][2] + b0;
            float v3 = acc[mi][ni][3] + b1;
            if (act == 1) {
                v0 = 0.5f*v0*(1.0f + erff(v0*0.70710678118654752440f));
                v1 = 0.5f*v1*(1.0f + erff(v1*0.70710678118654752440f));
                v2 = 0.5f*v2*(1.0f + erff(v2*0.70710678118654752440f));
                v3 = 0.5f*v3*(1.0f + erff(v3*0.70710678118654752440f));
            } else if (act == 2) {
                v0 *= SCL; v1 *= SCL; v2 *= SCL; v3 *= SCL;
            }
            if (Cf) {
                float* cp0 = Cf + (size_t)r*N + c;
                float* cp1 = Cf + (size_t)(r+8)*N + c;
                cp0[0] = v0; cp0[1] = v1;
                cp1[0] = v2; cp1[1] = v3;
            }
            if (Ch) {
                bf16 h0,l0,h1,l1,h2,l2,h3,l3;
                split_bf16(v0,h0,l0); split_bf16(v1,h1,l1);
                split_bf16(v2,h2,l2); split_bf16(v3,h3,l3);
                *(uint32_t*)(Ch + (size_t)r*N + c)     = pack2(h0,h1);
                *(uint32_t*)(Ch + (size_t)(r+8)*N + c) = pack2(h2,h3);
                *(uint32_t*)(Cl + (size_t)r*N + c)     = pack2(l0,l1);
                *(uint32_t*)(Cl + (size_t)(r+8)*N + c) = pack2(l2,l3);
            }
        }
    }
}

__global__ __launch_bounds__(256, 2)
void gemm_bf16x3(const bf16* __restrict__ Ah, const bf16* __restrict__ Al,
                 const bf16* __restrict__ Bh, const bf16* __restrict__ Bl,
                 const float* __restrict__ bias, float* __restrict__ Cf,
                 bf16* __restrict__ Ch, bf16* __restrict__ Cl,
                 int M, int N, int K, int act)
{
    extern __shared__ char gsm[];
    gemm_body(Ah, Al, Bh, Bl, bias, Cf, Ch, Cl, M, N, K, act,
              gsm, blockIdx.y*BM, blockIdx.x*BN);
}

// fused QKV: blockIdx.z selects weight/bias/output triple
__global__ __launch_bounds__(256, 2)
void gemm_qkv(const bf16* __restrict__ Ah, const bf16* __restrict__ Al,
              const bf16* __restrict__ BhQ, const bf16* __restrict__ BlQ,
              const bf16* __restrict__ BhK, const bf16* __restrict__ BlK,
              const bf16* __restrict__ BhV, const bf16* __restrict__ BlV,
              const float* __restrict__ bq, const float* __restrict__ bk2,
              const float* __restrict__ bv,
              bf16* __restrict__ Qh, bf16* __restrict__ Ql,
              bf16* __restrict__ Kh, bf16* __restrict__ Kl,
              bf16* __restrict__ Vh, bf16* __restrict__ Vl)
{
    extern __shared__ char gsm[];
    const int z = blockIdx.z;
    const bf16 *Bh, *Bl;
    const float* bias;
    bf16 *Ch, *Cl;
    int act;
    if (z == 0)      { Bh = BhQ; Bl = BlQ; bias = bq;  Ch = Qh; Cl = Ql; act = 2; }
    else if (z == 1) { Bh = BhK; Bl = BlK; bias = bk2; Ch = Kh; Cl = Kl; act = 0; }
    else             { Bh = BhV; Bl = BlV; bias = bv;  Ch = Vh; Cl = Vl; act = 0; }
    gemm_body(Ah, Al, Bh, Bl, bias, nullptr, Ch, Cl, NTOK, DMODEL, DMODEL, act,
              gsm, blockIdx.y*BM, blockIdx.x*BN);
}

// ---------------- MMA flash attention (bf16x3, causal) ----------------
#define AST 136
#define AQR 128
#define ATH2 256
#define ABUF (4*64*AST)
#define ATT_SMEM ((2*AQR*AST + 2*ABUF)*2)

__device__ __forceinline__ void attn_load_chunk(const bf16* Kh, const bf16* Kl,
                                                const bf16* Vh, const bf16* Vl,
                                                size_t gbase, int k0, uint32_t sbuf, int tid)
{
    const bf16* srcs[4] = {Kh, Kl, Vh, Vl};
    #pragma unroll
    for (int t = 0; t < 4; t++) {
        const bf16* p = srcs[t] + gbase + (size_t)k0*DMODEL;
        #pragma unroll
        for (int q = 0; q < 4; q++) {
            int i = q*ATH2 + tid;
            int r = i >> 4, c = i & 15;
            cp_async16(sbuf + (t*64 + r)*(AST*2) + c*16, p + (size_t)r*DMODEL + c*8);
        }
    }
    cp_commit();
}

__global__ __launch_bounds__(ATH2, 1)
void attn_mma(const bf16* __restrict__ Qh, const bf16* __restrict__ Ql,
              const bf16* __restrict__ Kh, const bf16* __restrict__ Kl,
              const bf16* __restrict__ Vh, const bf16* __restrict__ Vl,
              bf16* __restrict__ Oh, bf16* __restrict__ Ol)
{
    extern __shared__ char asmem[];
    const int tid = threadIdx.x;
    const int lane = tid & 31, w = tid >> 5;
    const int lq = lane >> 2, lr = lane & 3;
    const int q0 = blockIdx.x * AQR;
    const int h = blockIdx.y, b = blockIdx.z;
    const size_t gbase = ((size_t)b*SEQ)*DMODEL + h*DHEAD;

    bf16* Qs_h = (bf16*)asmem;
    bf16* Qs_l = Qs_h + AQR*AST;
    bf16* bufs = Qs_l + AQR*AST;

    {
        const bf16* srcs[2] = {Qh, Ql};
        #pragma unroll
        for (int t = 0; t < 2; t++) {
            const bf16* p = srcs[t] + gbase + (size_t)q0*DMODEL;
            uint32_t dst = smem_u32(Qs_h + t*AQR*AST);
            #pragma unroll
            for (int q = 0; q < 8; q++) {
                int i = q*ATH2 + tid;
                int r = i >> 4, c = i & 15;
                cp_async16(dst + r*(AST*2) + c*16, p + (size_t)r*DMODEL + c*8);
            }
        }
        attn_load_chunk(Kh, Kl, Vh, Vl, gbase, 0, smem_u32(bufs), tid);
    }

    float o[16][4];
    #pragma unroll
    for (int i = 0; i < 16; i++) {
        #pragma unroll
        for (int j = 0; j < 4; j++) o[i][j] = 0.f;
    }
    float m0v = -1e30f, m1v = -1e30f, l0v = 0.f, l1v = 0.f;

    const int qb = w * 16;
    const int row0 = q0 + qb + lq, row1 = row0 + 8;
    const int nch = q0/64 + 2;

    #pragma unroll 1
    for (int ch = 0; ch < nch; ++ch) {
        const int k0 = ch * 64;
        const bf16* Ks_h = bufs + (ch & 1)*ABUF;
        const bf16* Ks_l = Ks_h + 64*AST;
        const bf16* Vs_h = Ks_h + 2*64*AST;
        const bf16* Vs_l = Ks_h + 3*64*AST;

        if (ch + 1 < nch) {
            attn_load_chunk(Kh, Kl, Vh, Vl, gbase, k0 + 64, smem_u32(bufs + ((ch+1)&1)*ABUF), tid);
            cp_wait<1>();
        } else {
            cp_wait<0>();
        }
        __syncthreads();

        float s[8][4];
        #pragma unroll
        for (int i = 0; i < 8; i++) {
            #pragma unroll
            for (int j = 0; j < 4; j++) s[i][j] = 0.f;
        }
        #pragma unroll
        for (int ks = 0; ks < 8; ks++) {
            const int kk = ks*16 + 2*lr;
            uint32_t ah[4], al[4];
            ah[0] = *(const uint32_t*)(Qs_h + (qb+lq)*AST + kk);
            ah[1] = *(const uint32_t*)(Qs_h + (qb+lq+8)*AST + kk);
            ah[2] = *(const uint32_t*)(Qs_h + (qb+lq)*AST + kk + 8);
            ah[3] = *(const uint32_t*)(Qs_h + (qb+lq+8)*AST + kk + 8);
            al[0] = *(const uint32_t*)(Qs_l + (qb+lq)*AST + kk);
            al[1] = *(const uint32_t*)(Qs_l + (qb+lq+8)*AST + kk);
            al[2] = *(const uint32_t*)(Qs_l + (qb+lq)*AST + kk + 8);
            al[3] = *(const uint32_t*)(Qs_l + (qb+lq+8)*AST + kk + 8);
            #pragma unroll
            for (int ni = 0; ni < 8; ni++) {
                const int col = ni*8 + lq;
                uint32_t bh[2], bl[2];
                bh[0] = *(const uint32_t*)(Ks_h + col*AST + kk);
                bh[1] = *(const uint32_t*)(Ks_h + col*AST + kk + 8);
                bl[0] = *(const uint32_t*)(Ks_l + col*AST + kk);
                bl[1] = *(const uint32_t*)(Ks_l + col*AST + kk + 8);
                mma_bf16(s[ni], ah, bh);
                mma_bf16(s[ni], ah, bl);
                mma_bf16(s[ni], al, bh);
            }
        }

        #pragma unroll
        for (int ni = 0; ni < 8; ni++) {
            const int c0 = k0 + ni*8 + 2*lr;
            if (c0     > row0) s[ni][0] = -1e30f;
            if (c0 + 1 > row0) s[ni][1] = -1e30f;
            if (c0     > row1) s[ni][2] = -1e30f;
            if (c0 + 1 > row1) s[ni][3] = -1e30f;
        }

        float mx0 = m0v, mx1 = m1v;
        #pragma unroll
        for (int ni = 0; ni < 8; ni++) {
            mx0 = fmaxf(mx0, fmaxf(s[ni][0], s[ni][1]));
            mx1 = fmaxf(mx1, fmaxf(s[ni][2], s[ni][3]));
        }
        mx0 = fmaxf(mx0, __shfl_xor_sync(~0u, mx0, 1));
        mx0 = fmaxf(mx0, __shfl_xor_sync(~0u, mx0, 2));
        mx1 = fmaxf(mx1, __shfl_xor_sync(~0u, mx1, 1));
        mx1 = fmaxf(mx1, __shfl_xor_sync(~0u, mx1, 2));
        float c0f = __expf(m0v - mx0), c1f = __expf(m1v - mx1);
        float ls0 = 0.f, ls1 = 0.f;
        #pragma unroll
        for (int ni = 0; ni < 8; ni++) {
            s[ni][0] = __expf(s[ni][0] - mx0);
            s[ni][1] = __expf(s[ni][1] - mx0);
            s[ni][2] = __expf(s[ni][2] - mx1);
            s[ni][3] = __expf(s[ni][3] - mx1);
            ls0 += s[ni][0] + s[ni][1];
            ls1 += s[ni][2] + s[ni][3];
        }
        ls0 += __shfl_xor_sync(~0u, ls0, 1);
        ls0 += __shfl_xor_sync(~0u, ls0, 2);
        ls1 += __shfl_xor_sync(~0u, ls1, 1);
        ls1 += __shfl_xor_sync(~0u, ls1, 2);
        m0v = mx0; m1v = mx1;
        l0v = l0v*c0f + ls0;
        l1v = l1v*c1f + ls1;
        #pragma unroll
        for (int nd = 0; nd < 16; nd++) {
            o[nd][0] *= c0f; o[nd][1] *= c0f;
            o[nd][2] *= c1f; o[nd][3] *= c1f;
        }

        #pragma unroll
        for (int ks = 0; ks < 4; ks++) {
            bf16 hh[8], ll[8];
            split_bf16(s[2*ks][0],   hh[0], ll[0]);
            split_bf16(s[2*ks][1],   hh[1], ll[1]);
            split_bf16(s[2*ks][2],   hh[2], ll[2]);
            split_bf16(s[2*ks][3],   hh[3], ll[3]);
            split_bf16(s[2*ks+1][0], hh[4], ll[4]);
            split_bf16(s[2*ks+1][1], hh[5], ll[5]);
            split_bf16(s[2*ks+1][2], hh[6], ll[6]);
            split_bf16(s[2*ks+1][3], hh[7], ll[7]);
            uint32_t ah[4], al[4];
            ah[0] = pack2(hh[0], hh[1]); ah[1] = pack2(hh[2], hh[3]);
            ah[2] = pack2(hh[4], hh[5]); ah[3] = pack2(hh[6], hh[7]);
            al[0] = pack2(ll[0], ll[1]); al[1] = pack2(ll[2], ll[3]);
            al[2] = pack2(ll[4], ll[5]); al[3] = pack2(ll[6], ll[7]);
            const int vrow = ks*16 + (lane & 15);
            #pragma unroll
            for (int nd = 0; nd < 16; nd++) {
                uint32_t bh[2], bl[2];
                ldsm_x2_t(bh[0], bh[1], smem_u32(Vs_h + vrow*AST + nd*8));
                ldsm_x2_t(bl[0], bl[1], smem_u32(Vs_l + vrow*AST + nd*8));
                mma_bf16(o[nd], ah, bh);
                mma_bf16(o[nd], ah, bl);
                mma_bf16(o[nd], al, bh);
            }
        }
        __syncthreads();
    }

    const float inv0 = 1.f / l0v, inv1 = 1.f / l1v;
    const size_t r0 = ((size_t)b*SEQ + row0)*DMODEL + h*DHEAD;
    const size_t r1 = ((size_t)b*SEQ + row1)*DMODEL + h*DHEAD;
    #pragma unroll
    for (int nd = 0; nd < 16; nd++) {
        const int c = nd*8 + 2*lr;
        bf16 h0,l0,h1,l1,h2,l2,h3,l3;
        split_bf16(o[nd][0]*inv0, h0, l0);
        split_bf16(o[nd][1]*inv0, h1, l1);
        split_bf16(o[nd][2]*inv1, h2, l2);
        split_bf16(o[nd][3]*inv1, h3, l3);
        *(uint32_t*)(Oh + r0 + c) = pack2(h0, h1);
        *(uint32_t*)(Ol + r0 + c) = pack2(l0, l1);
        *(uint32_t*)(Oh + r1 + c) = pack2(h2, h3);
        *(uint32_t*)(Ol + r1 + c) = pack2(l2, l3);
    }
}

// ---------------- fused residual + LayerNorm (+ optional splits) ----------------
__global__ __launch_bounds__(256)
void ln_residual(const float* __restrict__ x, const float* __restrict__ r,
                 const float* __restrict__ g, const float* __restrict__ be,
                 float* __restrict__ out, bf16* __restrict__ oh, bf16* __restrict__ ol)
{
    const int row = blockIdx.x, t = threadIdx.x;
    const float* xp = x + (size_t)row*DMODEL;
    const float* rp = r + (size_t)row*DMODEL;
    float v[8], s = 0.f, s2 = 0.f;
    #pragma unroll
    for (int i = 0; i < 8; i++) {
        int c = t + i*256;
        float vv = xp[c]+rp[c];
        v[i] = vv; s += vv; s2 += vv*vv;
    }
    __shared__ float red[64];
    #pragma unroll
    for (int o = 16; o > 0; o >>= 1) {
        s  += __shfl_xor_sync(~0u,s,o);
        s2 += __shfl_xor_sync(~0u,s2,o);
    }
    int wid = t>>5, lid = t&31;
    if (lid == 0) { red[wid] = s; red[32+wid] = s2; }
    __syncthreads();
    if (wid == 0) {
        float a = (lid<8)?red[lid]:0.f, bsum = (lid<8)?red[32+lid]:0.f;
        #pragma unroll
        for (int o = 4; o > 0; o >>= 1) {
            a    += __shfl_xor_sync(~0u,a,o);
            bsum += __shfl_xor_sync(~0u,bsum,o);
        }
        if (lid == 0) { red[0] = a; red[1] = bsum; }
    }
    __syncthreads();
    float mean = red[0]*(1.f/DMODEL);
    float var  = red[1]*(1.f/DMODEL) - mean*mean;
    float rstd = rsqrtf(var + LN_EPS);
    #pragma unroll
    for (int i = 0; i < 8; i++) {
        int c = t + i*256;
        float y = g[c]*(v[i]-mean)*rstd + be[c];
        if (out) out[(size_t)row*DMODEL + c] = y;
        if (oh) {
            bf16 hh, lll;
            split_bf16(y, hh, lll);
            oh[(size_t)row*DMODEL + c] = hh;
            ol[(size_t)row*DMODEL + c] = lll;
        }
    }
}

// ---------------- launch ----------------
static float* SYM(const void* s){ void* p; cudaGetSymbolAddress(&p, (const void*)s); return (float*)p; }

extern "C" void kernel_launch(void* const* d_in, const int* in_sizes, int n_in,
                              void* d_out, int out_size)
{
    (void)in_sizes; (void)n_in; (void)out_size;
    const float* x  = (const float*)d_in[0];
    const float* Wq = (const float*)d_in[2];  const float* bq = (const float*)d_in[3];
    const float* Wk = (const float*)d_in[4];  const float* bk = (const float*)d_in[5];
    const float* Wv = (const float*)d_in[6];  const float* bv = (const float*)d_in[7];
    const float* Wo = (const float*)d_in[8];  const float* bo = (const float*)d_in[9];
    const float* W1 = (const float*)d_in[10]; const float* b1 = (const float*)d_in[11];
    const float* W2 = (const float*)d_in[12]; const float* b2 = (const float*)d_in[13];
    const float* g1 = (const float*)d_in[14]; const float* be1= (const float*)d_in[15];
    const float* g2 = (const float*)d_in[16]; const float* be2= (const float*)d_in[17];
    float* out = (float*)d_out;

    float *Tb = SYM(g_TMP), *X1b = SYM(g_X1);
    bf16 *xh = (bf16*)SYM(g_xh),  *xl = (bf16*)SYM(g_xl);
    bf16 *Qh = (bf16*)SYM(g_Qh),  *Ql = (bf16*)SYM(g_Ql);
    bf16 *Kh = (bf16*)SYM(g_Kh),  *Kl = (bf16*)SYM(g_Kl);
    bf16 *Vh = (bf16*)SYM(g_Vh),  *Vl = (bf16*)SYM(g_Vl);
    bf16 *Abh= (bf16*)SYM(g_Abh), *Abl= (bf16*)SYM(g_Abl);
    bf16 *X1h= (bf16*)SYM(g_X1h), *X1l= (bf16*)SYM(g_X1l);
    bf16 *H1h= (bf16*)SYM(g_H1h), *H1l= (bf16*)SYM(g_H1l);
    bf16 *WqTh=(bf16*)SYM(g_WqTh),*WqTl=(bf16*)SYM(g_WqTl);
    bf16 *WkTh=(bf16*)SYM(g_WkTh),*WkTl=(bf16*)SYM(g_WkTl);
    bf16 *WvTh=(bf16*)SYM(g_WvTh),*WvTl=(bf16*)SYM(g_WvTl);
    bf16 *WoTh=(bf16*)SYM(g_WoTh),*WoTl=(bf16*)SYM(g_WoTl);
    bf16 *W1Th=(bf16*)SYM(g_W1Th),*W1Tl=(bf16*)SYM(g_W1Tl);
    bf16 *W2Th=(bf16*)SYM(g_W2Th),*W2Tl=(bf16*)SYM(g_W2Tl);

    cudaFuncSetAttribute(gemm_bf16x3, cudaFuncAttributeMaxDynamicSharedMemorySize, GEMM_SMEM);
    cudaFuncSetAttribute(gemm_qkv,    cudaFuncAttributeMaxDynamicSharedMemorySize, GEMM_SMEM);
    cudaFuncSetAttribute(attn_mma,    cudaFuncAttributeMaxDynamicSharedMemorySize, ATT_SMEM);

    // side stream + events (created once; host resources only, reused every call)
    static cudaStream_t s2 = nullptr;
    static cudaEvent_t evFork = nullptr, evJoin = nullptr;
    if (!s2) {
        cudaStreamCreateWithFlags(&s2, cudaStreamNonBlocking);
        cudaEventCreateWithFlags(&evFork, cudaEventDisableTiming);
        cudaEventCreateWithFlags(&evJoin, cudaEventDisableTiming);
    }

    const int M = NTOK;
    dim3 tb(32,8);
    dim3 gDD(DMODEL/BN, M/BM);
    dim3 gQKV(DMODEL/BN, M/BM, 3);
    dim3 gDF(DFF/BN,    M/BM);
    const int nDD4 = NTOK*DMODEL/4;

    // fork side stream off the capture-origin stream
    cudaEventRecord(evFork, 0);
    cudaStreamWaitEvent(s2, evFork, 0);

    // main stream: x split + QKV weight splits + QKV gemm + attention
    act_split<<<(nDD4+255)/256, 256>>>(x, xh, xl, nDD4);
    wsplit_T<<<dim3(DMODEL/32, DMODEL/32), tb>>>(Wq, WqTh, WqTl, DMODEL, DMODEL);
    wsplit_T<<<dim3(DMODEL/32, DMODEL/32), tb>>>(Wk, WkTh, WkTl, DMODEL, DMODEL);
    wsplit_T<<<dim3(DMODEL/32, DMODEL/32), tb>>>(Wv, WvTh, WvTl, DMODEL, DMODEL);

    // side stream: Wo/W1/W2 splits overlap gemm_qkv + attention
    wsplit_T<<<dim3(DMODEL/32, DMODEL/32), tb, 0, s2>>>(Wo, WoTh, WoTl, DMODEL, DMODEL);
    wsplit_T<<<dim3(DFF/32,    DMODEL/32), tb, 0, s2>>>(W1, W1Th, W1Tl, DMODEL, DFF);
    wsplit_T<<<dim3(DMODEL/32, DFF/32),    tb, 0, s2>>>(W2, W2Th, W2Tl, DFF, DMODEL);
    cudaEventRecord(evJoin, s2);

    gemm_qkv<<<gQKV, 256, GEMM_SMEM>>>(xh, xl,
                                       WqTh, WqTl, WkTh, WkTl, WvTh, WvTl,
                                       bq, bk, bv, Qh, Ql, Kh, Kl, Vh, Vl);

    attn_mma<<<dim3(SEQ/AQR, NHEAD, BATCH), ATH2, ATT_SMEM>>>(Qh, Ql, Kh, Kl, Vh, Vl, Abh, Abl);

    // join before first consumer of side-stream results
    cudaStreamWaitEvent(0, evJoin, 0);

    gemm_bf16x3<<<gDD, 256, GEMM_SMEM>>>(Abh, Abl, WoTh, WoTl, bo, Tb, nullptr, nullptr, M, DMODEL, DMODEL, 0);
    ln_residual<<<NTOK, 256>>>(x, Tb, g1, be1, X1b, X1h, X1l);

    gemm_bf16x3<<<gDF, 256, GEMM_SMEM>>>(X1h, X1l, W1Th, W1Tl, b1, nullptr, H1h, H1l, M, DFF, DMODEL, 1);
    gemm_bf16x3<<<gDD, 256, GEMM_SMEM>>>(H1h, H1l, W2Th, W2Tl, b2, Tb, nullptr, nullptr, M, DMODEL, DFF, 0);

    ln_residual<<<NTOK, 256>>>(X1b, Tb, g2, be2, out, nullptr, nullptr);
}